// round 2
// baseline (speedup 1.0000x reference)
#include <cuda_runtime.h>

// DeformableFusionAcrossFocus: B=2, C=64, N=16, H=96, W=96, K=3, PAD=1
// Restructured: out[o,n] = b + sum_k W0[k,n]*Z_k[o,s0] + W1[k,n]*Z_k[o,s1],
//               Z_k = w_def[:,:,k] @ X   (dense GEMM, gather moved to epilogue)

#define CTA      512
#define NSITES   16
#define NC       64
#define NN       16
#define HW       9216      // 96*96
#define XSTRIDE  20        // per-site stride (16 data + 4 pad, keeps 16B align, kills STS conflicts)
#define XROW     (NSITES*XSTRIDE)   // 320 floats per c-row
#define ZWARP    1090      // per-warp Z/staging buffer (>= 16*64 and >= 64*17, even for 8B align)

// ---- shared memory layout (in floats) ----
#define OFF_X     0
#define SZ_X      (NC*XROW)              // 20480
#define OFF_Z     (OFF_X + SZ_X)         // 20480
#define SZ_Z      (NSITES*ZWARP)         // 17440
#define OFF_WDEF  (OFF_Z + SZ_Z)         // 37920  layout [k][c][o]
#define SZ_WDEF   (3*NC*NC)              // 12288
#define OFF_WOFF  (OFF_WDEF + SZ_WDEF)   // 50208  layout [k][c][o6]
#define SZ_WOFF   (3*NC*6)               // 1152
#define OFF_CW0   (OFF_WOFF + SZ_WOFF)   // 51360  [site][k][n]
#define OFF_CW1   (OFF_CW0 + 768)
#define OFF_CS0   (OFF_CW1 + 768)
#define OFF_CS1   (OFF_CS0 + 768)
#define OFF_BDEF  (OFF_CS1 + 768)        // 54432
#define OFF_BOFF  (OFF_BDEF + 64)        // 54496
#define SMEM_FLOATS (OFF_BOFF + 8)       // 54504
#define SMEM_BYTES  (SMEM_FLOATS * 4)    // 218016

typedef unsigned long long ull;

__device__ __forceinline__ ull pk2(float x, float y) {
    ull r; asm("mov.b64 %0, {%1, %2};" : "=l"(r) : "f"(x), "f"(y)); return r;
}
__device__ __forceinline__ void upk2(ull v, float& x, float& y) {
    asm("mov.b64 {%0, %1}, %2;" : "=f"(x), "=f"(y) : "l"(v));
}
__device__ __forceinline__ void fma2(ull& d, ull a, ull b) {
    // d = a*b + d, packed f32x2 (sm_103a dual-rate fp32 path)
    asm("fma.rn.f32x2 %0, %1, %2, %0;" : "+l"(d) : "l"(a), "l"(b));
}

__global__ void __launch_bounds__(CTA, 1)
deform_fuse_kernel(const float* __restrict__ x,
                   const float* __restrict__ w_off,
                   const float* __restrict__ b_off,
                   const float* __restrict__ w_def,
                   const float* __restrict__ b_def,
                   float* __restrict__ out)
{
    extern __shared__ float smem[];
    const int tid = threadIdx.x;
    const int bid = blockIdx.x;           // 0..1151
    const int b   = bid / 576;            // 576 = 96 * (96/16)
    const int h   = (bid / 6) % 96;
    const int w0  = (bid % 6) * NSITES;
    const long sbase = (long)h * 96 + w0;

    float* Xs  = smem + OFF_X;
    float* Zs  = smem + OFF_Z;
    float* WD  = smem + OFF_WDEF;
    float* WO  = smem + OFF_WOFF;
    float* CW0 = smem + OFF_CW0;
    float* CW1 = smem + OFF_CW1;
    int*   CS0 = (int*)(smem + OFF_CS0);
    int*   CS1 = (int*)(smem + OFF_CS1);
    float* BD  = smem + OFF_BDEF;
    float* BO  = smem + OFF_BOFF;

    // ---------------- cooperative loads ----------------
    {
        const float* xb = x + ((long)b * NC) * NN * HW + sbase;
        for (int idx = tid; idx < NC * NN * NSITES; idx += CTA) {
            int c = idx >> 8, n = (idx >> 4) & 15, s = idx & 15;
            Xs[c * XROW + s * XSTRIDE + n] = xb[((long)c * NN + n) * HW + s];
        }
        for (int idx = tid; idx < SZ_WDEF; idx += CTA) {
            int o = idx / 192, r = idx - o * 192, c = r / 3, k = r - c * 3;
            WD[k * 4096 + c * 64 + o] = w_def[idx];
        }
        for (int idx = tid; idx < SZ_WOFF; idx += CTA) {
            int o = idx / 192, r = idx - o * 192, c = r / 3, k = r - c * 3;
            WO[k * 384 + c * 6 + o] = w_off[idx];
        }
        if (tid < 64) BD[tid] = b_def[tid];
        if (tid < 6)  BO[tid] = b_off[tid];
    }
    __syncthreads();

    const int warp = tid >> 5;
    const int lane = tid & 31;
    const int site = warp;                       // one warp per site
    const float* Xsite = Xs + site * XSTRIDE;
    float* Zw = Zs + site * ZWARP;

    // ---------------- offset conv + interp coefficients (lanes 0..15, lane = n) ----------------
    if (lane < 16) {
        const int n = lane;
        float a0 = BO[0], a1 = BO[1], a2 = BO[2], a3 = BO[3], a4 = BO[4], a5 = BO[5];
        #pragma unroll
        for (int k = 0; k < 3; k++) {
            int np = n - 1 + k;
            if (np >= 0 && np < 16) {
                const float* wo = WO + k * 384;
                #pragma unroll 8
                for (int c = 0; c < 64; c++) {
                    float xv = Xsite[c * XROW + np];
                    const float* w = wo + c * 6;
                    a0 += w[0] * xv; a1 += w[1] * xv; a2 += w[2] * xv;
                    a3 += w[3] * xv; a4 += w[4] * xv; a5 += w[5] * xv;
                }
            }
        }
        float offy[3] = { a0, a2, a4 };   // channels 0,2,4
        float offx[3] = { a1, a3, a5 };   // channels 1,3,5
        #pragma unroll
        for (int k = 0; k < 3; k++) {
            float px  = (float)(n - 1 + k) + offx[k];
            float x0f = floorf(px);
            float fx  = px - x0f;
            int   x0i = (int)x0f;
            int   x1i = x0i + 1;
            float wy  = fmaxf(0.f, 1.f - fabsf(offy[k]));
            float W0  = (x0i >= 0 && x0i < 16) ? (1.f - fx) * wy : 0.f;
            float W1  = (x1i >= 0 && x1i < 16) ? fx * wy : 0.f;
            int   s0  = min(max(x0i, 0), 15);
            int   s1  = min(max(x1i, 0), 15);
            int ci = site * 48 + k * 16 + n;
            CW0[ci] = W0; CW1[ci] = W1; CS0[ci] = s0; CS1[ci] = s1;
        }
    }
    __syncwarp();

    // ---------------- main compute: per-k GEMM + gather epilogue ----------------
    const int o0 = 2 * lane, o1 = 2 * lane + 1;
    float out0[16], out1[16];
    {
        float bd0 = BD[o0], bd1 = BD[o1];
        #pragma unroll
        for (int n = 0; n < 16; n++) { out0[n] = bd0; out1[n] = bd1; }
    }

    #pragma unroll
    for (int k = 0; k < 3; k++) {
        // Z_k[o, n'] = sum_c w_def[o,c,k] * X[c,n'] ; lane owns rows o0,o1, n' packed in f32x2 pairs
        ull z0[8], z1[8];
        #pragma unroll
        for (int j = 0; j < 8; j++) { z0[j] = 0ull; z1[j] = 0ull; }

        const float* wk = WD + k * 4096 + o0;
        #pragma unroll 4
        for (int c = 0; c < 64; c++) {
            float2 w2 = *(const float2*)(wk + c * 64);       // (w[o0,c,k], w[o1,c,k])
            ull ww0 = pk2(w2.x, w2.x);
            ull ww1 = pk2(w2.y, w2.y);
            const ulonglong2* xp = (const ulonglong2*)(Xsite + c * XROW);
            ulonglong2 xa = xp[0], xb = xp[1], xc = xp[2], xd = xp[3];
            fma2(z0[0], ww0, xa.x); fma2(z0[1], ww0, xa.y);
            fma2(z0[2], ww0, xb.x); fma2(z0[3], ww0, xb.y);
            fma2(z0[4], ww0, xc.x); fma2(z0[5], ww0, xc.y);
            fma2(z0[6], ww0, xd.x); fma2(z0[7], ww0, xd.y);
            fma2(z1[0], ww1, xa.x); fma2(z1[1], ww1, xa.y);
            fma2(z1[2], ww1, xb.x); fma2(z1[3], ww1, xb.y);
            fma2(z1[4], ww1, xc.x); fma2(z1[5], ww1, xc.y);
            fma2(z1[6], ww1, xd.x); fma2(z1[7], ww1, xd.y);
        }

        // stage Z to smem as [n'][o]  (so gather reads one LDS.64 per tap)
        #pragma unroll
        for (int j = 0; j < 8; j++) {
            float va, vb;
            upk2(z0[j], va, vb);
            Zw[(2 * j) * 64 + o0] = va; Zw[(2 * j + 1) * 64 + o0] = vb;
            upk2(z1[j], va, vb);
            Zw[(2 * j) * 64 + o1] = va; Zw[(2 * j + 1) * 64 + o1] = vb;
        }
        __syncwarp();

        // gather epilogue
        const float* cw0 = CW0 + site * 48 + k * 16;
        const float* cw1 = CW1 + site * 48 + k * 16;
        const int*   cs0 = CS0 + site * 48 + k * 16;
        const int*   cs1 = CS1 + site * 48 + k * 16;
        #pragma unroll
        for (int n = 0; n < 16; n++) {
            float W0 = cw0[n], W1 = cw1[n];
            int s0 = cs0[n], s1 = cs1[n];
            float2 g0 = *(const float2*)(Zw + s0 * 64 + o0);  // (Z[o0,s0], Z[o1,s0])
            float2 g1 = *(const float2*)(Zw + s1 * 64 + o0);
            out0[n] += W0 * g0.x + W1 * g1.x;
            out1[n] += W0 * g0.y + W1 * g1.y;
        }
        __syncwarp();
    }

    // ---------------- stage outputs [o*17+n] per warp, then coalesced CTA-wide store ----------------
    #pragma unroll
    for (int n = 0; n < 16; n++) {
        Zw[o0 * 17 + n] = out0[n];
        Zw[o1 * 17 + n] = out1[n];
    }
    __syncthreads();

    float* ob = out + ((long)b * NC) * NN * HW + sbase;
    for (int idx = tid; idx < NC * NN * NSITES; idx += CTA) {
        int o = idx >> 8, n = (idx >> 4) & 15, s = idx & 15;
        ob[((long)o * NN + n) * HW + s] = Zs[s * ZWARP + o * 17 + n];
    }
}

extern "C" void kernel_launch(void* const* d_in, const int* in_sizes, int n_in,
                              void* d_out, int out_size)
{
    const float* x     = (const float*)d_in[0];
    const float* w_off = (const float*)d_in[1];
    const float* b_off = (const float*)d_in[2];
    const float* w_def = (const float*)d_in[3];
    const float* b_def = (const float*)d_in[4];
    float* out = (float*)d_out;

    cudaFuncSetAttribute(deform_fuse_kernel,
                         cudaFuncAttributeMaxDynamicSharedMemorySize, SMEM_BYTES);

    // 2 (B) * 96 (H) * 6 (W/16) = 1152 CTAs, 512 threads each
    deform_fuse_kernel<<<1152, 512, SMEM_BYTES>>>(x, w_off, b_off, w_def, b_def, out);
}

// round 4
// speedup vs baseline: 1.2323x; 1.2323x over previous
#include <cuda_runtime.h>
#include <cuda_bf16.h>
#include <cstdint>

// DeformableFusionAcrossFocus via mma.sync bf16 (HMMA, legal on plain sm_103 target)
// B=2, C=64, N=16, H=W=96, K=3. CTA = 16 w-sites, 8 warps, warp = 2 sites (32 M rows).
// GEMM: D[m=(site,n'), col] = sum_c X[c,n'] * W[col,c]
//   cols 0..191  : Z_k[o]   (k=col>>6, o=col&63), W = w_def[o][c][k]
//   cols 192..209: Zoff     (kk=(col-192)/6, j=(col-192)%6), W = w_off[j][c][kk]
//   cols 210..215: zero pad          (27 chunks of 8 cols)
// 3-pass bf16 split: Ah*Bh + Ah*Bl + Al*Bh  (fp32 accumulate).

#define HW 9216
#define NCHUNK 27

// ---- smem byte layout ----
#define SM_AF   0                    // A fragments [pass2][MT16][ks4][lane32] uint4 = 65536
#define SM_BF   65536                // B fragments [chunk27][ks4][pass2][lane32] uint2 = 55296
#define SM_SCR  120832               // X staging (64*276 floats) then per-warp Z/off buffers = 70656
#define SM_BD   191488               // 64 floats
#define SM_BO   191744               // 6 floats (+pad)
#define SMEM_TOTAL 191776

__device__ __forceinline__ void mma16816(float& d0, float& d1, float& d2, float& d3,
                                         uint4 a, uint2 b) {
    asm volatile(
        "mma.sync.aligned.m16n8k16.row.col.f32.bf16.bf16.f32 "
        "{%0,%1,%2,%3}, {%4,%5,%6,%7}, {%8,%9}, {%0,%1,%2,%3};"
        : "+f"(d0), "+f"(d1), "+f"(d2), "+f"(d3)
        : "r"(a.x), "r"(a.y), "r"(a.z), "r"(a.w), "r"(b.x), "r"(b.y));
}

__device__ __forceinline__ uint32_t pkbf(float v0, float v1, uint32_t& lo) {
    __nv_bfloat16 h0 = __float2bfloat16(v0), h1 = __float2bfloat16(v1);
    float r0 = v0 - __bfloat162float(h0);
    float r1 = v1 - __bfloat162float(h1);
    __nv_bfloat16 l0 = __float2bfloat16(r0), l1 = __float2bfloat16(r1);
    lo = (uint32_t)__bfloat16_as_ushort(l0) | ((uint32_t)__bfloat16_as_ushort(l1) << 16);
    return (uint32_t)__bfloat16_as_ushort(h0) | ((uint32_t)__bfloat16_as_ushort(h1) << 16);
}

__global__ void __launch_bounds__(256, 1)
deform_hmma_kernel(const float* __restrict__ x,
                   const float* __restrict__ w_off,
                   const float* __restrict__ b_off,
                   const float* __restrict__ w_def,
                   const float* __restrict__ b_def,
                   float* __restrict__ out)
{
    extern __shared__ char smem[];
    uint4* AF  = (uint4*)(smem + SM_AF);
    uint2* BF  = (uint2*)(smem + SM_BF);
    float* SCR = (float*)(smem + SM_SCR);
    float* BD  = (float*)(smem + SM_BD);
    float* BO  = (float*)(smem + SM_BO);

    const int tid  = threadIdx.x;
    const int wid  = tid >> 5;
    const int lane = tid & 31;
    const int g    = lane >> 2;       // fragment row group
    const int q    = lane & 3;        // fragment col group

    const int bid = blockIdx.x;       // 0..1151
    const int b   = bid / 576;
    const int h   = (bid / 6) % 96;
    const int w0  = (bid % 6) * 16;
    const long xbase = (long)b * (64 * 16 * HW) + (long)h * 96 + w0;

    if (tid < 64) BD[tid] = b_def[tid];
    if (tid < 6)  BO[tid] = b_off[tid];

    // ---------------- stage X[c][s][n] -> SCR[c*276 + s*17 + n] ----------------
    {
        const float* xb = x + xbase;
        #pragma unroll 8
        for (int i = tid; i < 16384; i += 256) {
            int s = i & 15, n = (i >> 4) & 15, c = i >> 8;
            SCR[c * 276 + s * 17 + n] = xb[(long)(c * 16 + n) * HW + s];
        }
    }

    // ---------------- B fragments from gmem (L2-resident weights) ----------------
    #pragma unroll 2
    for (int idx = tid; idx < NCHUNK * 4 * 32; idx += 256) {
        int l = idx & 31, rem = idx >> 5;
        int ks = rem & 3, chunk = rem >> 2;
        int ncol = chunk * 8 + (l >> 2);
        int c0 = ks * 16 + (l & 3) * 2;
        float v[4];
        #pragma unroll
        for (int i = 0; i < 4; i++) {
            int c = c0 + (i >> 1) * 8 + (i & 1);
            float w = 0.f;
            if (ncol < 192) {
                int kk = ncol >> 6, o = ncol & 63;
                w = __ldg(w_def + o * 192 + c * 3 + kk);
            } else if (ncol < 210) {
                int t = ncol - 192, kk = t / 6, j = t - 6 * kk;
                w = __ldg(w_off + j * 192 + c * 3 + kk);
            }
            v[i] = w;
        }
        uint32_t l0, l1;
        uint32_t h0 = pkbf(v[0], v[1], l0);
        uint32_t h1 = pkbf(v[2], v[3], l1);
        BF[((chunk * 4 + ks) * 2 + 0) * 32 + l] = make_uint2(h0, h1);
        BF[((chunk * 4 + ks) * 2 + 1) * 32 + l] = make_uint2(l0, l1);
    }
    __syncthreads();   // X staging visible

    // ---------------- A fragments (warp builds its own 2 M-tiles) ----------------
    #pragma unroll
    for (int p = 0; p < 2; p++) {
        const int MT = wid * 2 + p;                // = local site
        const float* base = SCR + MT * 17;
        #pragma unroll
        for (int ks = 0; ks < 4; ks++) {
            int c0 = ks * 16 + q * 2;
            float v0 = base[(c0    ) * 276 + g    ];
            float v1 = base[(c0 + 1) * 276 + g    ];
            float v2 = base[(c0    ) * 276 + g + 8];
            float v3 = base[(c0 + 1) * 276 + g + 8];
            float v4 = base[(c0 + 8) * 276 + g    ];
            float v5 = base[(c0 + 9) * 276 + g    ];
            float v6 = base[(c0 + 8) * 276 + g + 8];
            float v7 = base[(c0 + 9) * 276 + g + 8];
            uint32_t la0, la1, la2, la3;
            uint32_t a0 = pkbf(v0, v1, la0);
            uint32_t a1 = pkbf(v2, v3, la1);
            uint32_t a2 = pkbf(v4, v5, la2);
            uint32_t a3 = pkbf(v6, v7, la3);
            AF[(( 0 + MT) * 4 + ks) * 32 + lane] = make_uint4(a0, a1, a2, a3);
            AF[((16 + MT) * 4 + ks) * 32 + lane] = make_uint4(la0, la1, la2, la3);
        }
    }
    __syncthreads();   // all fragments visible; SCR free for reuse

    // ---------------- per-warp independent pipeline ----------------
    float* Zw = SCR + wid * 2176;          // 32 rows x 68 (Z) / 32 x 24 (offsets)
    const int n  = lane & 15;
    const int hs = lane >> 4;              // 0/1: which of the warp's 2 sites

    float acc[2][4];

    // --- offsets (chunks 24..26) ---
    #pragma unroll
    for (int c3 = 0; c3 < 3; c3++) {
        const int chunk = 24 + c3;
        #pragma unroll
        for (int mt = 0; mt < 2; mt++)
            acc[mt][0] = acc[mt][1] = acc[mt][2] = acc[mt][3] = 0.f;
        #pragma unroll
        for (int ks = 0; ks < 4; ks++) {
            uint2 bh = BF[((chunk * 4 + ks) * 2 + 0) * 32 + lane];
            uint2 bl = BF[((chunk * 4 + ks) * 2 + 1) * 32 + lane];
            #pragma unroll
            for (int mt = 0; mt < 2; mt++) {
                uint4 ah = AF[(( 0 + wid * 2 + mt) * 4 + ks) * 32 + lane];
                uint4 al = AF[((16 + wid * 2 + mt) * 4 + ks) * 32 + lane];
                mma16816(acc[mt][0], acc[mt][1], acc[mt][2], acc[mt][3], ah, bh);
                mma16816(acc[mt][0], acc[mt][1], acc[mt][2], acc[mt][3], ah, bl);
                mma16816(acc[mt][0], acc[mt][1], acc[mt][2], acc[mt][3], al, bh);
            }
        }
        #pragma unroll
        for (int mt = 0; mt < 2; mt++) {
            int r = mt * 16 + g, cb = c3 * 8 + q * 2;
            *(float2*)(Zw + (r    ) * 24 + cb) = make_float2(acc[mt][0], acc[mt][1]);
            *(float2*)(Zw + (r + 8) * 24 + cb) = make_float2(acc[mt][2], acc[mt][3]);
        }
    }
    __syncwarp();

    // --- interpolation coefficients (lane owns row (hs, n)) ---
    float W0c[3], W1c[3];
    int   s0c[3], s1c[3];
    {
        float offv[6];
        #pragma unroll
        for (int j = 0; j < 6; j++) {
            float v = BO[j];
            #pragma unroll
            for (int kk = 0; kk < 3; kk++) {
                int np = n - 1 + kk;
                if (np >= 0 && np < 16)
                    v += Zw[(hs * 16 + np) * 24 + kk * 6 + j];
            }
            offv[j] = v;
        }
        #pragma unroll
        for (int k = 0; k < 3; k++) {
            float px  = (float)(n - 1 + k) + offv[2 * k + 1];
            float x0f = floorf(px);
            float fx  = px - x0f;
            int x0i = (int)x0f, x1i = x0i + 1;
            float wy = fmaxf(0.f, 1.f - fabsf(offv[2 * k]));
            W0c[k] = (x0i >= 0 && x0i < 16) ? (1.f - fx) * wy : 0.f;
            W1c[k] = (x1i >= 0 && x1i < 16) ? fx * wy : 0.f;
            s0c[k] = min(max(x0i, 0), 15);
            s1c[k] = min(max(x1i, 0), 15);
        }
    }
    __syncwarp();   // offsets consumed; Zw free for Z tiles

    // --- output accumulators ---
    float acco[64];
    #pragma unroll
    for (int j = 0; j < 16; j++) {
        float4 bd4 = ((const float4*)BD)[j];
        acco[4 * j + 0] = bd4.x; acco[4 * j + 1] = bd4.y;
        acco[4 * j + 2] = bd4.z; acco[4 * j + 3] = bd4.w;
    }

    // --- Z_k tiles + gather epilogue ---
    #pragma unroll 1
    for (int g3 = 0; g3 < 3; g3++) {
        #pragma unroll 1
        for (int cc = 0; cc < 8; cc++) {
            const int chunk = g3 * 8 + cc;
            #pragma unroll
            for (int mt = 0; mt < 2; mt++)
                acc[mt][0] = acc[mt][1] = acc[mt][2] = acc[mt][3] = 0.f;
            #pragma unroll
            for (int ks = 0; ks < 4; ks++) {
                uint2 bh = BF[((chunk * 4 + ks) * 2 + 0) * 32 + lane];
                uint2 bl = BF[((chunk * 4 + ks) * 2 + 1) * 32 + lane];
                #pragma unroll
                for (int mt = 0; mt < 2; mt++) {
                    uint4 ah = AF[(( 0 + wid * 2 + mt) * 4 + ks) * 32 + lane];
                    uint4 al = AF[((16 + wid * 2 + mt) * 4 + ks) * 32 + lane];
                    mma16816(acc[mt][0], acc[mt][1], acc[mt][2], acc[mt][3], ah, bh);
                    mma16816(acc[mt][0], acc[mt][1], acc[mt][2], acc[mt][3], ah, bl);
                    mma16816(acc[mt][0], acc[mt][1], acc[mt][2], acc[mt][3], al, bh);
                }
            }
            #pragma unroll
            for (int mt = 0; mt < 2; mt++) {
                int r = mt * 16 + g, cb = cc * 8 + q * 2;
                *(float2*)(Zw + (r    ) * 68 + cb) = make_float2(acc[mt][0], acc[mt][1]);
                *(float2*)(Zw + (r + 8) * 68 + cb) = make_float2(acc[mt][2], acc[mt][3]);
            }
        }
        __syncwarp();

        {
            const float* p0 = Zw + (hs * 16 + s0c[g3]) * 68;
            const float* p1 = Zw + (hs * 16 + s1c[g3]) * 68;
            const float Wa = W0c[g3], Wb = W1c[g3];
            #pragma unroll
            for (int j = 0; j < 16; j++) {
                float4 g0 = ((const float4*)p0)[j];
                float4 g1 = ((const float4*)p1)[j];
                acco[4 * j + 0] += Wa * g0.x + Wb * g1.x;
                acco[4 * j + 1] += Wa * g0.y + Wb * g1.y;
                acco[4 * j + 2] += Wa * g0.z + Wb * g1.z;
                acco[4 * j + 3] += Wa * g0.w + Wb * g1.w;
            }
        }
        __syncwarp();
    }

    // --- store: out[((b*64+o)*16+n)*HW + h*96 + w0 + ls], ls = 2*wid + hs ---
    {
        float* ob = out + xbase + (2 * wid + hs) + (long)n * HW;
        #pragma unroll
        for (int o = 0; o < 64; o++)
            ob[(long)o * (16 * HW)] = acco[o];
    }
}

extern "C" void kernel_launch(void* const* d_in, const int* in_sizes, int n_in,
                              void* d_out, int out_size)
{
    const float* x     = (const float*)d_in[0];
    const float* w_off = (const float*)d_in[1];
    const float* b_off = (const float*)d_in[2];
    const float* w_def = (const float*)d_in[3];
    const float* b_def = (const float*)d_in[4];
    float* out = (float*)d_out;

    cudaFuncSetAttribute(deform_hmma_kernel,
                         cudaFuncAttributeMaxDynamicSharedMemorySize, SMEM_TOTAL);

    // 2 (B) * 96 (H) * 6 (W/16) = 1152 CTAs, 256 threads
    deform_hmma_kernel<<<1152, 256, SMEM_TOTAL>>>(x, w_off, b_off, w_def, b_def, out);
}

// round 5
// speedup vs baseline: 2.2071x; 1.7911x over previous
#include <cuda_runtime.h>
#include <cuda_bf16.h>
#include <cstdint>

// DeformableFusionAcrossFocus via mma.sync bf16 (HMMA), R4: A-in-regs, 16 warps, staged store.
// B=2, C=64, N=16, H=W=96, K=3. CTA = 16 w-sites, 16 warps, warp = 1 site (16 M rows).
// GEMM: D[m=n', col] = sum_c X[c,n'] * W[col,c]
//   cols 0..191  : Z_k[o]  (k=col>>6, o=col&63), W = w_def[o][c][k]
//   cols 192..209: Zoff    (kk=(col-192)/6, j=(col-192)%6), W = w_off[j][c][kk]
//   cols 210..215: zero pad         (27 chunks of 8 cols)
// 3-pass bf16 split: Ah*Bh + Ah*Bl + Al*Bh (fp32 accumulate).

#define HW 9216
#define NCHUNK 27

// ---- smem byte layout ----
#define SM_BF   0                    // B fragments [chunk27][ks4][pass2][lane32] uint2 = 55296
#define SM_SCR  55296                // X staging 64*276 floats = 70656; reused as Zw then STG2
#define SM_BD   125952               // 64 floats
#define SM_BO   126208               // 6 floats (+pad)
#define SMEM_TOTAL 126240

__device__ __forceinline__ void mma16816(float& d0, float& d1, float& d2, float& d3,
                                         uint4 a, uint2 b) {
    asm volatile(
        "mma.sync.aligned.m16n8k16.row.col.f32.bf16.bf16.f32 "
        "{%0,%1,%2,%3}, {%4,%5,%6,%7}, {%8,%9}, {%0,%1,%2,%3};"
        : "+f"(d0), "+f"(d1), "+f"(d2), "+f"(d3)
        : "r"(a.x), "r"(a.y), "r"(a.z), "r"(a.w), "r"(b.x), "r"(b.y));
}

__device__ __forceinline__ uint32_t pkbf(float v0, float v1, uint32_t& lo) {
    __nv_bfloat16 h0 = __float2bfloat16(v0), h1 = __float2bfloat16(v1);
    float r0 = v0 - __bfloat162float(h0);
    float r1 = v1 - __bfloat162float(h1);
    __nv_bfloat16 l0 = __float2bfloat16(r0), l1 = __float2bfloat16(r1);
    lo = (uint32_t)__bfloat16_as_ushort(l0) | ((uint32_t)__bfloat16_as_ushort(l1) << 16);
    return (uint32_t)__bfloat16_as_ushort(h0) | ((uint32_t)__bfloat16_as_ushort(h1) << 16);
}

__global__ void __launch_bounds__(512, 1)
deform_hmma2_kernel(const float* __restrict__ x,
                    const float* __restrict__ w_off,
                    const float* __restrict__ b_off,
                    const float* __restrict__ w_def,
                    const float* __restrict__ b_def,
                    float* __restrict__ out)
{
    extern __shared__ char smem[];
    uint2* BF  = (uint2*)(smem + SM_BF);
    float* SCR = (float*)(smem + SM_SCR);
    float* BD  = (float*)(smem + SM_BD);
    float* BO  = (float*)(smem + SM_BO);

    const int tid  = threadIdx.x;
    const int wid  = tid >> 5;        // warp = local site
    const int lane = tid & 31;
    const int g    = lane >> 2;       // fragment row group
    const int q    = lane & 3;        // fragment col group

    const int bid = blockIdx.x;       // 0..1151
    const int b   = bid / 576;
    const int h   = (bid / 6) % 96;
    const int w0  = (bid % 6) * 16;
    const long xbase = (long)b * (64 * 16 * HW) + (long)h * 96 + w0;

    if (tid < 64) BD[tid] = b_def[tid];
    if (tid < 6)  BO[tid] = b_off[tid];

    // ---------------- stage X[c][s][n] -> SCR[c*276 + s*17 + n] ----------------
    {
        const float* xb = x + xbase;
        #pragma unroll 8
        for (int i = tid; i < 16384; i += 512) {
            int s = i & 15, n = (i >> 4) & 15, c = i >> 8;
            SCR[c * 276 + s * 17 + n] = xb[(long)(c * 16 + n) * HW + s];
        }
    }

    // ---------------- B fragments from gmem (L2-resident weights) ----------------
    for (int idx = tid; idx < NCHUNK * 4 * 32; idx += 512) {
        int l = idx & 31, rem = idx >> 5;
        int ks = rem & 3, chunk = rem >> 2;
        int ncol = chunk * 8 + (l >> 2);
        int c0 = ks * 16 + (l & 3) * 2;
        float v[4];
        #pragma unroll
        for (int i = 0; i < 4; i++) {
            int c = c0 + (i >> 1) * 8 + (i & 1);
            float w = 0.f;
            if (ncol < 192) {
                int kk = ncol >> 6, o = ncol & 63;
                w = __ldg(w_def + o * 192 + c * 3 + kk);
            } else if (ncol < 210) {
                int t = ncol - 192, kk = t / 6, j = t - 6 * kk;
                w = __ldg(w_off + j * 192 + c * 3 + kk);
            }
            v[i] = w;
        }
        uint32_t l0, l1;
        uint32_t h0 = pkbf(v[0], v[1], l0);
        uint32_t h1 = pkbf(v[2], v[3], l1);
        BF[((chunk * 4 + ks) * 2 + 0) * 32 + l] = make_uint2(h0, h1);
        BF[((chunk * 4 + ks) * 2 + 1) * 32 + l] = make_uint2(l0, l1);
    }
    __syncthreads();   // X staging + B fragments visible

    // ---------------- A fragments -> registers (warp's own site) ----------------
    uint4 ah[4], al[4];
    {
        const float* base = SCR + wid * 17;
        #pragma unroll
        for (int ks = 0; ks < 4; ks++) {
            int c0 = ks * 16 + q * 2;
            float v0 = base[(c0    ) * 276 + g    ];
            float v1 = base[(c0 + 1) * 276 + g    ];
            float v2 = base[(c0    ) * 276 + g + 8];
            float v3 = base[(c0 + 1) * 276 + g + 8];
            float v4 = base[(c0 + 8) * 276 + g    ];
            float v5 = base[(c0 + 9) * 276 + g    ];
            float v6 = base[(c0 + 8) * 276 + g + 8];
            float v7 = base[(c0 + 9) * 276 + g + 8];
            uint32_t la0, la1, la2, la3;
            uint32_t a0 = pkbf(v0, v1, la0);
            uint32_t a1 = pkbf(v2, v3, la1);
            uint32_t a2 = pkbf(v4, v5, la2);
            uint32_t a3 = pkbf(v6, v7, la3);
            ah[ks] = make_uint4(a0, a1, a2, a3);
            al[ks] = make_uint4(la0, la1, la2, la3);
        }
    }
    __syncthreads();   // everyone done reading X staging; SCR reusable as Zw

    float* Zw = SCR + wid * 1088;      // 16 rows x 68 (Z) / 16 x 24 (offsets)
    const int n  = lane & 15;
    const int oh = lane >> 4;          // o half: o in [oh*32, oh*32+32)

    // ---------------- offsets (chunks 24..26) ----------------
    #pragma unroll
    for (int c3 = 0; c3 < 3; c3++) {
        const int chunk = 24 + c3;
        float p0 = 0.f, p1 = 0.f, p2 = 0.f, p3 = 0.f;   // ks 0,1 chain
        float r0 = 0.f, r1 = 0.f, r2 = 0.f, r3 = 0.f;   // ks 2,3 chain
        #pragma unroll
        for (int ks = 0; ks < 4; ks++) {
            uint2 bh = BF[((chunk * 4 + ks) * 2 + 0) * 32 + lane];
            uint2 bl = BF[((chunk * 4 + ks) * 2 + 1) * 32 + lane];
            if (ks < 2) {
                mma16816(p0, p1, p2, p3, ah[ks], bh);
                mma16816(p0, p1, p2, p3, ah[ks], bl);
                mma16816(p0, p1, p2, p3, al[ks], bh);
            } else {
                mma16816(r0, r1, r2, r3, ah[ks], bh);
                mma16816(r0, r1, r2, r3, ah[ks], bl);
                mma16816(r0, r1, r2, r3, al[ks], bh);
            }
        }
        int cb = c3 * 8 + q * 2;
        *(float2*)(Zw + (g    ) * 24 + cb) = make_float2(p0 + r0, p1 + r1);
        *(float2*)(Zw + (g + 8) * 24 + cb) = make_float2(p2 + r2, p3 + r3);
    }
    __syncwarp();

    // ---------------- interpolation coefficients (lane owns row n) ----------------
    float W0c[3], W1c[3];
    int   s0c[3], s1c[3];
    {
        float offv[6];
        #pragma unroll
        for (int j = 0; j < 6; j++) {
            float v = BO[j];
            #pragma unroll
            for (int kk = 0; kk < 3; kk++) {
                int np = n - 1 + kk;
                if (np >= 0 && np < 16)
                    v += Zw[np * 24 + kk * 6 + j];
            }
            offv[j] = v;
        }
        #pragma unroll
        for (int k = 0; k < 3; k++) {
            float px  = (float)(n - 1 + k) + offv[2 * k + 1];
            float x0f = floorf(px);
            float fx  = px - x0f;
            int x0i = (int)x0f, x1i = x0i + 1;
            float wy = fmaxf(0.f, 1.f - fabsf(offv[2 * k]));
            W0c[k] = (x0i >= 0 && x0i < 16) ? (1.f - fx) * wy : 0.f;
            W1c[k] = (x1i >= 0 && x1i < 16) ? fx * wy : 0.f;
            s0c[k] = min(max(x0i, 0), 15);
            s1c[k] = min(max(x1i, 0), 15);
        }
    }
    __syncwarp();   // offsets consumed; Zw free for Z tiles

    // ---------------- output accumulators (o = oh*32 + i) ----------------
    float acco[32];
    #pragma unroll
    for (int j = 0; j < 8; j++) {
        float4 bd4 = ((const float4*)BD)[oh * 8 + j];
        acco[4 * j + 0] = bd4.x; acco[4 * j + 1] = bd4.y;
        acco[4 * j + 2] = bd4.z; acco[4 * j + 3] = bd4.w;
    }

    // ---------------- Z_k tiles + gather epilogue ----------------
    #pragma unroll 1
    for (int g3 = 0; g3 < 3; g3++) {
        #pragma unroll 1
        for (int cc = 0; cc < 8; cc++) {
            const int chunk = g3 * 8 + cc;
            float p0 = 0.f, p1 = 0.f, p2 = 0.f, p3 = 0.f;
            float r0 = 0.f, r1 = 0.f, r2 = 0.f, r3 = 0.f;
            #pragma unroll
            for (int ks = 0; ks < 4; ks++) {
                uint2 bh = BF[((chunk * 4 + ks) * 2 + 0) * 32 + lane];
                uint2 bl = BF[((chunk * 4 + ks) * 2 + 1) * 32 + lane];
                if (ks < 2) {
                    mma16816(p0, p1, p2, p3, ah[ks], bh);
                    mma16816(p0, p1, p2, p3, ah[ks], bl);
                    mma16816(p0, p1, p2, p3, al[ks], bh);
                } else {
                    mma16816(r0, r1, r2, r3, ah[ks], bh);
                    mma16816(r0, r1, r2, r3, ah[ks], bl);
                    mma16816(r0, r1, r2, r3, al[ks], bh);
                }
            }
            int cb = cc * 8 + q * 2;
            *(float2*)(Zw + (g    ) * 68 + cb) = make_float2(p0 + r0, p1 + r1);
            *(float2*)(Zw + (g + 8) * 68 + cb) = make_float2(p2 + r2, p3 + r3);
        }
        __syncwarp();

        {
            const float* t0 = Zw + s0c[g3] * 68 + oh * 32;
            const float* t1 = Zw + s1c[g3] * 68 + oh * 32;
            const float Wa = W0c[g3], Wb = W1c[g3];
            #pragma unroll
            for (int j = 0; j < 8; j++) {
                float4 g0 = ((const float4*)t0)[j];
                float4 g1 = ((const float4*)t1)[j];
                acco[4 * j + 0] += Wa * g0.x + Wb * g1.x;
                acco[4 * j + 1] += Wa * g0.y + Wb * g1.y;
                acco[4 * j + 2] += Wa * g0.z + Wb * g1.z;
                acco[4 * j + 3] += Wa * g0.w + Wb * g1.w;
            }
        }
        __syncwarp();
    }

    // ---------------- staged coalesced store ----------------
    // STG2[on*16 + (s ^ (on&15))], on = o*16 + n, s = site = wid (swizzled for banks)
    __syncthreads();   // all warps done with Zw
    {
        float* STG2 = SCR;
        const int sw = wid ^ n;        // on&15 == n
        #pragma unroll
        for (int i = 0; i < 32; i++) {
            int on = (oh * 32 + i) * 16 + n;
            STG2[on * 16 + sw] = acco[i];
        }
    }
    __syncthreads();
    {
        const float* STG2 = SCR;
        float* ob = out + xbase;
        #pragma unroll 8
        for (int idx = tid; idx < 16384; idx += 512) {
            int s = idx & 15, on = idx >> 4;
            ob[(long)on * HW + s] = STG2[on * 16 + (s ^ (on & 15))];
        }
    }
}

extern "C" void kernel_launch(void* const* d_in, const int* in_sizes, int n_in,
                              void* d_out, int out_size)
{
    const float* x     = (const float*)d_in[0];
    const float* w_off = (const float*)d_in[1];
    const float* b_off = (const float*)d_in[2];
    const float* w_def = (const float*)d_in[3];
    const float* b_def = (const float*)d_in[4];
    float* out = (float*)d_out;

    cudaFuncSetAttribute(deform_hmma2_kernel,
                         cudaFuncAttributeMaxDynamicSharedMemorySize, SMEM_TOTAL);

    // 2 (B) * 96 (H) * 6 (W/16) = 1152 CTAs, 512 threads
    deform_hmma2_kernel<<<1152, 512, SMEM_TOTAL>>>(x, w_off, b_off, w_def, b_def, out);
}

// round 6
// speedup vs baseline: 2.4370x; 1.1042x over previous
#include <cuda_runtime.h>
#include <cuda_fp16.h>
#include <cstdint>

// DeformableFusionAcrossFocus via mma.sync fp16 (HMMA), R5: A-split 2-pass, B prefetch.
// B=2, C=64, N=16, H=W=96, K=3. CTA = 16 w-sites, 16 warps, warp = 1 site (16 M rows).
// GEMM: D[m=n', col] = sum_c X[c,n'] * W[col,c]
//   cols 0..191  : Z_k[o]  (k=col>>6, o=col&63), W = w_def[o][c][k]
//   cols 192..209: Zoff    (kk=(col-192)/6, j=(col-192)%6), W = w_off[j][c][kk]
//   cols 210..215: zero pad         (27 chunks of 8 cols)
// 2-pass fp16 A-split: (Ah + Al) * B, fp32 accumulate.  B-quant error ~1.4e-4 RMS.

#define HW 9216
#define NCHUNK 27

// ---- smem byte layout ----
#define SM_BF   0                    // B fragments [chunk27][ks4][lane32] uint2 = 27648
#define SM_SCR  27648                // X staging 64*276 floats = 70656; reused as Zw then STG2
#define SM_BD   98304                // 64 floats
#define SM_BO   98560                // 6 floats (+pad)
#define SMEM_TOTAL 98592

__device__ __forceinline__ void mma16816(float& d0, float& d1, float& d2, float& d3,
                                         uint4 a, uint2 b) {
    asm volatile(
        "mma.sync.aligned.m16n8k16.row.col.f32.f16.f16.f32 "
        "{%0,%1,%2,%3}, {%4,%5,%6,%7}, {%8,%9}, {%0,%1,%2,%3};"
        : "+f"(d0), "+f"(d1), "+f"(d2), "+f"(d3)
        : "r"(a.x), "r"(a.y), "r"(a.z), "r"(a.w), "r"(b.x), "r"(b.y));
}

__device__ __forceinline__ uint32_t pkh(__half h0, __half h1) {
    return (uint32_t)__half_as_ushort(h0) | ((uint32_t)__half_as_ushort(h1) << 16);
}
// split-pack: hi = fp16(v), lo = fp16(v - hi)
__device__ __forceinline__ uint32_t pkhs(float v0, float v1, uint32_t& lo) {
    __half h0 = __float2half_rn(v0), h1 = __float2half_rn(v1);
    float r0 = v0 - __half2float(h0);
    float r1 = v1 - __half2float(h1);
    lo = pkh(__float2half_rn(r0), __float2half_rn(r1));
    return pkh(h0, h1);
}

__global__ void __launch_bounds__(512, 1)
deform_hmma3_kernel(const float* __restrict__ x,
                    const float* __restrict__ w_off,
                    const float* __restrict__ b_off,
                    const float* __restrict__ w_def,
                    const float* __restrict__ b_def,
                    float* __restrict__ out)
{
    extern __shared__ char smem[];
    uint2* BF  = (uint2*)(smem + SM_BF);
    float* SCR = (float*)(smem + SM_SCR);
    float* BD  = (float*)(smem + SM_BD);
    float* BO  = (float*)(smem + SM_BO);

    const int tid  = threadIdx.x;
    const int wid  = tid >> 5;        // warp = local site
    const int lane = tid & 31;
    const int g    = lane >> 2;       // fragment row group
    const int q    = lane & 3;        // fragment col group

    const int bid = blockIdx.x;       // 0..1151
    const int b   = bid / 576;
    const int h   = (bid / 6) % 96;
    const int w0  = (bid % 6) * 16;
    const long xbase = (long)b * (64 * 16 * HW) + (long)h * 96 + w0;

    if (tid < 64) BD[tid] = b_def[tid];
    if (tid < 6)  BO[tid] = b_off[tid];

    // ---------------- stage X[c][s][n] -> SCR[c*276 + s*17 + n] ----------------
    {
        const float* xb = x + xbase;
        #pragma unroll 8
        for (int i = tid; i < 16384; i += 512) {
            int s = i & 15, n = (i >> 4) & 15, c = i >> 8;
            SCR[c * 276 + s * 17 + n] = xb[(long)(c * 16 + n) * HW + s];
        }
    }

    // ---------------- B fragments (single fp16) from gmem ----------------
    for (int idx = tid; idx < NCHUNK * 4 * 32; idx += 512) {
        int l = idx & 31, rem = idx >> 5;
        int ks = rem & 3, chunk = rem >> 2;
        int ncol = chunk * 8 + (l >> 2);
        int c0 = ks * 16 + (l & 3) * 2;
        float v[4];
        #pragma unroll
        for (int i = 0; i < 4; i++) {
            int c = c0 + (i >> 1) * 8 + (i & 1);
            float w = 0.f;
            if (ncol < 192) {
                int kk = ncol >> 6, o = ncol & 63;
                w = __ldg(w_def + o * 192 + c * 3 + kk);
            } else if (ncol < 210) {
                int t = ncol - 192, kk = t / 6, j = t - 6 * kk;
                w = __ldg(w_off + j * 192 + c * 3 + kk);
            }
            v[i] = w;
        }
        BF[(chunk * 4 + ks) * 32 + l] =
            make_uint2(pkh(__float2half_rn(v[0]), __float2half_rn(v[1])),
                       pkh(__float2half_rn(v[2]), __float2half_rn(v[3])));
    }
    __syncthreads();   // X staging + B fragments visible

    // ---------------- A fragments -> registers (warp's own site, fp16 hi/lo) ----------------
    uint4 ah[4], al[4];
    {
        const float* base = SCR + wid * 17;
        #pragma unroll
        for (int ks = 0; ks < 4; ks++) {
            int c0 = ks * 16 + q * 2;
            float v0 = base[(c0    ) * 276 + g    ];
            float v1 = base[(c0 + 1) * 276 + g    ];
            float v2 = base[(c0    ) * 276 + g + 8];
            float v3 = base[(c0 + 1) * 276 + g + 8];
            float v4 = base[(c0 + 8) * 276 + g    ];
            float v5 = base[(c0 + 9) * 276 + g    ];
            float v6 = base[(c0 + 8) * 276 + g + 8];
            float v7 = base[(c0 + 9) * 276 + g + 8];
            uint32_t la0, la1, la2, la3;
            uint32_t a0 = pkhs(v0, v1, la0);
            uint32_t a1 = pkhs(v2, v3, la1);
            uint32_t a2 = pkhs(v4, v5, la2);
            uint32_t a3 = pkhs(v6, v7, la3);
            ah[ks] = make_uint4(a0, a1, a2, a3);
            al[ks] = make_uint4(la0, la1, la2, la3);
        }
    }
    __syncthreads();   // everyone done reading X staging; SCR reusable as Zw

    const uint2* BFl = BF + lane;      // hoisted lane base
    float* Zw = SCR + wid * 1088;      // 16 rows x 68 (Z) / 16 x 24 (offsets)
    const int n  = lane & 15;
    const int oh = lane >> 4;          // o half: o in [oh*32, oh*32+32)

    // ---------------- offsets (chunks 24..26) ----------------
    #pragma unroll
    for (int c3 = 0; c3 < 3; c3++) {
        const int chunk = 24 + c3;
        float p0 = 0.f, p1 = 0.f, p2 = 0.f, p3 = 0.f;   // ks 0,1 chain
        float r0 = 0.f, r1 = 0.f, r2 = 0.f, r3 = 0.f;   // ks 2,3 chain
        #pragma unroll
        for (int ks = 0; ks < 4; ks++) {
            uint2 bb = BFl[(chunk * 4 + ks) * 32];
            if (ks < 2) {
                mma16816(p0, p1, p2, p3, ah[ks], bb);
                mma16816(p0, p1, p2, p3, al[ks], bb);
            } else {
                mma16816(r0, r1, r2, r3, ah[ks], bb);
                mma16816(r0, r1, r2, r3, al[ks], bb);
            }
        }
        int cb = c3 * 8 + q * 2;
        *(float2*)(Zw + (g    ) * 24 + cb) = make_float2(p0 + r0, p1 + r1);
        *(float2*)(Zw + (g + 8) * 24 + cb) = make_float2(p2 + r2, p3 + r3);
    }
    __syncwarp();

    // ---------------- interpolation coefficients (lane owns row n) ----------------
    float W0c[3], W1c[3];
    int   s0c[3], s1c[3];
    {
        float offv[6];
        #pragma unroll
        for (int j = 0; j < 6; j++) {
            float v = BO[j];
            #pragma unroll
            for (int kk = 0; kk < 3; kk++) {
                int np = n - 1 + kk;
                if (np >= 0 && np < 16)
                    v += Zw[np * 24 + kk * 6 + j];
            }
            offv[j] = v;
        }
        #pragma unroll
        for (int k = 0; k < 3; k++) {
            float px  = (float)(n - 1 + k) + offv[2 * k + 1];
            float x0f = floorf(px);
            float fx  = px - x0f;
            int x0i = (int)x0f, x1i = x0i + 1;
            float wy = fmaxf(0.f, 1.f - fabsf(offv[2 * k]));
            W0c[k] = (x0i >= 0 && x0i < 16) ? (1.f - fx) * wy : 0.f;
            W1c[k] = (x1i >= 0 && x1i < 16) ? fx * wy : 0.f;
            s0c[k] = min(max(x0i, 0), 15);
            s1c[k] = min(max(x1i, 0), 15);
        }
    }
    __syncwarp();   // offsets consumed; Zw free for Z tiles

    // ---------------- output accumulators (o = oh*32 + i) ----------------
    float acco[32];
    #pragma unroll
    for (int j = 0; j < 8; j++) {
        float4 bd4 = ((const float4*)BD)[oh * 8 + j];
        acco[4 * j + 0] = bd4.x; acco[4 * j + 1] = bd4.y;
        acco[4 * j + 2] = bd4.z; acco[4 * j + 3] = bd4.w;
    }

    // ---------------- Z_k tiles + gather epilogue ----------------
    #pragma unroll 1
    for (int g3 = 0; g3 < 3; g3++) {
        // prefetch first chunk's B frags
        uint2 bcur[4];
        #pragma unroll
        for (int ks = 0; ks < 4; ks++)
            bcur[ks] = BFl[((g3 * 8) * 4 + ks) * 32];

        #pragma unroll 1
        for (int cc = 0; cc < 8; cc++) {
            const int chunk = g3 * 8 + cc;
            // prefetch next chunk (clamped; harmless extra load on last iter)
            const int nxt = (chunk + 1 < 24) ? chunk + 1 : 23;
            uint2 bnxt[4];
            #pragma unroll
            for (int ks = 0; ks < 4; ks++)
                bnxt[ks] = BFl[(nxt * 4 + ks) * 32];

            float p0 = 0.f, p1 = 0.f, p2 = 0.f, p3 = 0.f;
            float r0 = 0.f, r1 = 0.f, r2 = 0.f, r3 = 0.f;
            mma16816(p0, p1, p2, p3, ah[0], bcur[0]);
            mma16816(r0, r1, r2, r3, ah[2], bcur[2]);
            mma16816(p0, p1, p2, p3, al[0], bcur[0]);
            mma16816(r0, r1, r2, r3, al[2], bcur[2]);
            mma16816(p0, p1, p2, p3, ah[1], bcur[1]);
            mma16816(r0, r1, r2, r3, ah[3], bcur[3]);
            mma16816(p0, p1, p2, p3, al[1], bcur[1]);
            mma16816(r0, r1, r2, r3, al[3], bcur[3]);

            int cb = cc * 8 + q * 2;
            *(float2*)(Zw + (g    ) * 68 + cb) = make_float2(p0 + r0, p1 + r1);
            *(float2*)(Zw + (g + 8) * 68 + cb) = make_float2(p2 + r2, p3 + r3);

            #pragma unroll
            for (int ks = 0; ks < 4; ks++) bcur[ks] = bnxt[ks];
        }
        __syncwarp();

        {
            const float* t0 = Zw + s0c[g3] * 68 + oh * 32;
            const float* t1 = Zw + s1c[g3] * 68 + oh * 32;
            const float Wa = W0c[g3], Wb = W1c[g3];
            #pragma unroll
            for (int j = 0; j < 8; j++) {
                float4 g0 = ((const float4*)t0)[j];
                float4 g1 = ((const float4*)t1)[j];
                acco[4 * j + 0] += Wa * g0.x + Wb * g1.x;
                acco[4 * j + 1] += Wa * g0.y + Wb * g1.y;
                acco[4 * j + 2] += Wa * g0.z + Wb * g1.z;
                acco[4 * j + 3] += Wa * g0.w + Wb * g1.w;
            }
        }
        __syncwarp();
    }

    // ---------------- staged coalesced store ----------------
    __syncthreads();   // all warps done with Zw
    {
        float* STG2 = SCR;
        const int sw = wid ^ n;        // swizzle (on&15 == n)
        #pragma unroll
        for (int i = 0; i < 32; i++) {
            int on = (oh * 32 + i) * 16 + n;
            STG2[on * 16 + sw] = acco[i];
        }
    }
    __syncthreads();
    {
        const float* STG2 = SCR;
        float* ob = out + xbase;
        #pragma unroll 8
        for (int idx = tid; idx < 16384; idx += 512) {
            int s = idx & 15, on = idx >> 4;
            ob[(long)on * HW + s] = STG2[on * 16 + (s ^ (on & 15))];
        }
    }
}

extern "C" void kernel_launch(void* const* d_in, const int* in_sizes, int n_in,
                              void* d_out, int out_size)
{
    const float* x     = (const float*)d_in[0];
    const float* w_off = (const float*)d_in[1];
    const float* b_off = (const float*)d_in[2];
    const float* w_def = (const float*)d_in[3];
    const float* b_def = (const float*)d_in[4];
    float* out = (float*)d_out;

    cudaFuncSetAttribute(deform_hmma3_kernel,
                         cudaFuncAttributeMaxDynamicSharedMemorySize, SMEM_TOTAL);

    // 2 (B) * 96 (H) * 6 (W/16) = 1152 CTAs, 512 threads
    deform_hmma3_kernel<<<1152, 512, SMEM_TOTAL>>>(x, w_off, b_off, w_def, b_def, out);
}